// round 3
// baseline (speedup 1.0000x reference)
#include <cuda_runtime.h>
#include <cuda_fp16.h>
#include <stdint.h>

#define D 128
#define DV 32              // float4 chunks per row
#define MAXN 50048
#define MAXE 1600000

__device__ int    g_row[MAXE];
__device__ int    g_col[MAXE];
__device__ int2   g_adj[MAXE];        // dst-sorted: {src, __float_as_int(dis[src])}
__device__ int    g_deg[MAXN];
__device__ int    g_cnt[MAXN];        // in-degree counts, then scatter cursors
__device__ int    g_start[MAXN + 1];  // CSR offsets by dst
__device__ float  g_dis[MAXN];
__device__ float  g_a[MAXN * D];      // aggregated features (fp32)
__device__ __half g_xh[MAXN * D];     // fp16 copy of x
__device__ __half g_hh[MAXN * D];     // fp16 hidden after layer 1
__device__ int    g_is64;

// ---------------------------------------------------------------------------
// Fused: dtype detect (block 0) + deg/cnt init (all blocks).
// int64 little-endian values < 2^32 -> every odd 32-bit word zero over 2048
// samples; int32 random indices make that astronomically unlikely.
// ---------------------------------------------------------------------------
__global__ void k_detect_init(const unsigned* p, int N) {
    int i = blockIdx.x * blockDim.x + threadIdx.x;
    if (i < N) { g_deg[i] = 1; g_cnt[i] = 0; }   // deg starts at 1 (self loop)
    if (blockIdx.x == 0) {
        __shared__ int any_nz;
        if (threadIdx.x == 0) any_nz = 0;
        __syncthreads();
        int local = 0;
        for (int k = 1 + 2 * threadIdx.x; k < 4096; k += 2 * blockDim.x)
            if (p[k]) local = 1;
        if (local) any_nz = 1;
        __syncthreads();
        if (threadIdx.x == 0) g_is64 = any_nz ? 0 : 1;
    }
}

// Parse edges (either dtype), store int32 row/col, count degrees.
__global__ void k_prep(const void* p, int E) {
    int e = blockIdx.x * blockDim.x + threadIdx.x;
    if (e >= E) return;
    int r, c;
    if (g_is64) {
        const long long* q = (const long long*)p;
        r = (int)q[e];
        c = (int)q[(long long)E + e];
    } else {
        const int* q = (const int*)p;
        r = q[e];
        c = q[E + e];
    }
    g_row[e] = r;
    g_col[e] = c;
    atomicAdd(&g_deg[r], 1);
    atomicAdd(&g_cnt[c], 1);
}

// Single-block: exclusive scan of g_cnt -> g_start, zero cursors, compute dis.
__global__ void k_scan_dis(int N, int E) {
    __shared__ int sh[1024];
    const int tid = threadIdx.x;
    const int per = (N + 1023) >> 10;
    const int base = tid * per;
    int s = 0;
    for (int i = 0; i < per; i++) {
        int idx = base + i;
        if (idx < N) s += g_cnt[idx];
    }
    sh[tid] = s;
    __syncthreads();
    for (int off = 1; off < 1024; off <<= 1) {
        int t = (tid >= off) ? sh[tid - off] : 0;
        __syncthreads();
        sh[tid] += t;
        __syncthreads();
    }
    int run = sh[tid] - s;   // exclusive prefix for this thread's range
    for (int i = 0; i < per; i++) {
        int idx = base + i;
        if (idx < N) {
            int c = g_cnt[idx];
            g_start[idx] = run;
            run += c;
            g_cnt[idx] = 0;
            g_dis[idx] = rsqrtf((float)g_deg[idx]);
        }
    }
    if (tid == 0) g_start[N] = E;
}

// Scatter edges into dst-sorted adjacency with per-edge weight dis[src].
__global__ void k_scatter(int E) {
    int e = blockIdx.x * blockDim.x + threadIdx.x;
    if (e >= E) return;
    int r = g_row[e];
    int c = g_col[e];
    int pos = g_start[c] + atomicAdd(&g_cnt[c], 1);
    g_adj[pos] = make_int2(r, __float_as_int(g_dis[r]));
}

// fp32 -> fp16 feature copy (x only; h's fp16 copy comes from GEMM-1 epilogue).
__global__ void k_half(const float4* __restrict__ src, uint2* __restrict__ dst, int n4) {
    int t = blockIdx.x * blockDim.x + threadIdx.x;
    if (t >= n4) return;
    float4 v = src[t];
    uint2 o;
    *(__half2*)&o.x = __floats2half2_rn(v.x, v.y);
    *(__half2*)&o.y = __floats2half2_rn(v.z, v.w);
    dst[t] = o;
}

// ---------------------------------------------------------------------------
// Aggregation: one warp per dst node, fp16 gather (256B/row), fp32 accum.
// Adjacency read 32-wide coalesced, distributed via shfl.
// dst = dis[n]*(sum_e dis[src]*x[src]) + dis[n]^2 * x[n]
// ---------------------------------------------------------------------------
__global__ void k_agg(const uint2* __restrict__ src, float4* __restrict__ dst, int N) {
    int w = (blockIdx.x * blockDim.x + threadIdx.x) >> 5;
    if (w >= N) return;
    const int lane = threadIdx.x & 31;
    const int beg = g_start[w];
    const int end = g_start[w + 1];

    float4 acc = make_float4(0.f, 0.f, 0.f, 0.f);
    for (int base = beg; base < end; base += 32) {
        int cnt = end - base;
        if (cnt > 32) cnt = 32;
        int2 e = (lane < cnt) ? g_adj[base + lane] : make_int2(0, 0);
        #pragma unroll 4
        for (int j = 0; j < cnt; j++) {
            int   s  = __shfl_sync(0xffffffffu, e.x, j);
            float wj = __int_as_float(__shfl_sync(0xffffffffu, e.y, j));
            uint2 p = src[(long)s * 32 + lane];
            float2 f0 = __half22float2(*(__half2*)&p.x);
            float2 f1 = __half22float2(*(__half2*)&p.y);
            acc.x += wj * f0.x; acc.y += wj * f0.y;
            acc.z += wj * f1.x; acc.w += wj * f1.y;
        }
    }

    float di = g_dis[w];
    float sw = di * di;
    uint2 ps = src[(long)w * 32 + lane];
    float2 s0 = __half22float2(*(__half2*)&ps.x);
    float2 s1 = __half22float2(*(__half2*)&ps.y);
    float4 o;
    o.x = di * acc.x + sw * s0.x;
    o.y = di * acc.y + sw * s0.y;
    o.z = di * acc.z + sw * s1.x;
    o.w = di * acc.w + sw * s1.y;
    dst[(long)w * 32 + lane] = o;
}

// ---------------------------------------------------------------------------
// GEMM: C[N,128] = A[N,128] @ W[128,128] + bias, optional ReLU.
// BM=128, BN=128, BK=32, 256 threads, 8x8 register tile.
// HALF_OUT stores __half (feeds next layer's fp16 gather), else float.
// ---------------------------------------------------------------------------
template <bool RELU, bool HALF_OUT>
__global__ void k_gemm(const float* __restrict__ A, const float* __restrict__ W,
                       const float* __restrict__ bias, void* __restrict__ Cv, int N) {
    __shared__ float As[32][129];   // [k][m]
    __shared__ float Ws[32][128];   // [k][n]

    const int tid = threadIdx.x;
    const int tm = tid >> 4;    // 0..15 -> 8 rows each
    const int tn = tid & 15;    // 0..15 -> 8 cols each
    const int row0 = blockIdx.x * 128;

    float acc[8][8];
    #pragma unroll
    for (int i = 0; i < 8; i++)
        #pragma unroll
        for (int j = 0; j < 8; j++) acc[i][j] = 0.f;

    for (int kk = 0; kk < D; kk += 32) {
        #pragma unroll
        for (int it = 0; it < 4; it++) {
            int idx = tid + it * 256;
            int m  = idx >> 3;       // row in tile (0..127)
            int k4 = idx & 7;        // float4 index along k (0..7)
            float4 v = make_float4(0.f, 0.f, 0.f, 0.f);
            int gr = row0 + m;
            if (gr < N) v = *(const float4*)(A + (long)gr * D + kk + k4 * 4);
            As[k4 * 4 + 0][m] = v.x;
            As[k4 * 4 + 1][m] = v.y;
            As[k4 * 4 + 2][m] = v.z;
            As[k4 * 4 + 3][m] = v.w;
        }
        #pragma unroll
        for (int it = 0; it < 4; it++) {
            int idx = tid + it * 256;
            int k  = idx >> 5;
            int n4 = idx & 31;
            *(float4*)&Ws[k][n4 * 4] = *(const float4*)(W + (kk + k) * D + n4 * 4);
        }
        __syncthreads();

        #pragma unroll 8
        for (int k = 0; k < 32; k++) {
            float a[8], b[8];
            #pragma unroll
            for (int j = 0; j < 8; j++) a[j] = As[k][tm * 8 + j];
            float4 b0 = *(const float4*)&Ws[k][tn * 8];
            float4 b1 = *(const float4*)&Ws[k][tn * 8 + 4];
            b[0] = b0.x; b[1] = b0.y; b[2] = b0.z; b[3] = b0.w;
            b[4] = b1.x; b[5] = b1.y; b[6] = b1.z; b[7] = b1.w;
            #pragma unroll
            for (int i = 0; i < 8; i++)
                #pragma unroll
                for (int j = 0; j < 8; j++)
                    acc[i][j] += a[i] * b[j];
        }
        __syncthreads();
    }

    float4 bv0 = *(const float4*)(bias + tn * 8);
    float4 bv1 = *(const float4*)(bias + tn * 8 + 4);
    #pragma unroll
    for (int i = 0; i < 8; i++) {
        int gr = row0 + tm * 8 + i;
        if (gr >= N) continue;
        float o[8];
        o[0] = acc[i][0] + bv0.x; o[1] = acc[i][1] + bv0.y;
        o[2] = acc[i][2] + bv0.z; o[3] = acc[i][3] + bv0.w;
        o[4] = acc[i][4] + bv1.x; o[5] = acc[i][5] + bv1.y;
        o[6] = acc[i][6] + bv1.z; o[7] = acc[i][7] + bv1.w;
        if (RELU) {
            #pragma unroll
            for (int j = 0; j < 8; j++) o[j] = fmaxf(o[j], 0.f);
        }
        if (HALF_OUT) {
            __half h8[8];
            #pragma unroll
            for (int j = 0; j < 8; j++) h8[j] = __float2half_rn(o[j]);
            *(uint4*)((__half*)Cv + (long)gr * D + tn * 8) = *(uint4*)h8;
        } else {
            float* C = (float*)Cv;
            *(float4*)(C + (long)gr * D + tn * 8)     = make_float4(o[0], o[1], o[2], o[3]);
            *(float4*)(C + (long)gr * D + tn * 8 + 4) = make_float4(o[4], o[5], o[6], o[7]);
        }
    }
}

extern "C" void kernel_launch(void* const* d_in, const int* in_sizes, int n_in,
                              void* d_out, int out_size) {
    const float* x  = (const float*)d_in[0];
    const void*  ei = d_in[1];
    const float* W1 = (const float*)d_in[2];
    const float* b1 = (const float*)d_in[3];
    const float* W2 = (const float*)d_in[4];
    const float* b2 = (const float*)d_in[5];
    float* out = (float*)d_out;

    const int N = in_sizes[0] / D;
    const int E = in_sizes[1] / 2;

    float*  a_ptr  = nullptr;
    __half* xh_ptr = nullptr;
    __half* hh_ptr = nullptr;
    cudaGetSymbolAddress((void**)&a_ptr,  g_a);
    cudaGetSymbolAddress((void**)&xh_ptr, g_xh);
    cudaGetSymbolAddress((void**)&hh_ptr, g_hh);

    const int T = 256;
    const int nGrid = (N + T - 1) / T;
    const int eGrid = (E + T - 1) / T;

    // ---- prep: detect+init, parse+counts, scan+dis, scatter ----
    k_detect_init<<<nGrid, T>>>((const unsigned*)ei, N);
    k_prep<<<eGrid, T>>>(ei, E);
    k_scan_dis<<<1, 1024>>>(N, E);
    k_scatter<<<eGrid, T>>>(E);

    // ---- fp16 copy of x ----
    const int n4 = N * DV;
    k_half<<<(n4 + T - 1) / T, T>>>((const float4*)x, (uint2*)xh_ptr, n4);

    const int aggGrid  = (N * 32 + T - 1) / T;
    const int gemmGrid = (N + 127) / 128;

    // ---- layer 1: a = Agg(x_h); h_h = half(relu(a @ W1 + b1)) ----
    k_agg<<<aggGrid, T>>>((const uint2*)xh_ptr, (float4*)a_ptr, N);
    k_gemm<true, true><<<gemmGrid, T>>>(a_ptr, W1, b1, hh_ptr, N);

    // ---- layer 2: a = Agg(h_h); out = a @ W2 + b2 ----
    k_agg<<<aggGrid, T>>>((const uint2*)hh_ptr, (float4*)a_ptr, N);
    k_gemm<false, false><<<gemmGrid, T>>>(a_ptr, W2, b2, out, N);
}